// round 15
// baseline (speedup 1.0000x reference)
#include <cuda_runtime.h>
#include <cuda_fp16.h>
#include <math.h>
#include <stdint.h>

#define U_   1024
#define D_   64
#define B_   4096
#define SPB  16        // samples per block (2 blocks per SM)
#define NTH  512
#define PADX 17
#define PADU 65
#define PADZ 18

// ---- device-global weight scratch (no allocs allowed) ----
__device__ float g_W0p[U_ * D_];        // masked W0, rows sorted by dh (bands contiguous)
__device__ float g_b0p[U_];
__device__ float g_b1p[U_];
__device__ float g_W1pT[U_ * U_];       // [c][r] masked W1^T, both perm'd (intermediate)
__device__ float g_W2pT[U_ * 2 * D_];   // [c][o] masked W2^T (band rows contiguous)
// A-fragment register images (fp16): frag id = ((v*32+w32)*2+mt)*2+kc, 32 lanes of uint4
__device__ uint4 g_W1f[63 * 32 * 2 * 2 * 32];

// units sorted by dh = u % 63
__device__ __forceinline__ int perm_of(int j, int& v) {
    int t;
    if (j < 272) { v = j / 17; t = j - v * 17; }
    else         { v = (j - 16) >> 4; t = (j - 16) & 15; }
    return v + 63 * t;
}
__device__ __forceinline__ int band_s0(int v)  { return (v <= 16) ? 17 * v : 16 * v + 16; }
__device__ __forceinline__ int band_cnt(int v) { return (v < 16) ? 17 : 16; }

// ---- packed fp32x2 helpers (Phase D) ----
__device__ __forceinline__ unsigned long long pack2(float lo, float hi) {
    unsigned long long r;
    asm("mov.b64 %0, {%1, %2};" : "=l"(r) : "f"(lo), "f"(hi));
    return r;
}
__device__ __forceinline__ void fma_f32x2(unsigned long long& d,
                                          unsigned long long a,
                                          unsigned long long b) {
    asm("fma.rn.f32x2 %0, %1, %2, %0;" : "+l"(d) : "l"(a), "l"(b));
}

// ---- mma fp16 helper ----
__device__ __forceinline__ void mma_f16(float* d, const uint4& a, const uint2& b) {
    asm volatile(
        "mma.sync.aligned.m16n8k16.row.col.f32.f16.f16.f32 "
        "{%0,%1,%2,%3},{%4,%5,%6,%7},{%8,%9},{%0,%1,%2,%3};"
        : "+f"(d[0]), "+f"(d[1]), "+f"(d[2]), "+f"(d[3])
        : "r"(a.x), "r"(a.y), "r"(a.z), "r"(a.w), "r"(b.x), "r"(b.y));
}

// ---- mbarrier / bulk-copy helpers ----
__device__ __forceinline__ uint32_t sm32(const void* p) {
    uint32_t a;
    asm("{ .reg .u64 t; cvta.to.shared.u64 t, %1; cvt.u32.u64 %0, t; }"
        : "=r"(a) : "l"(p));
    return a;
}
__device__ __forceinline__ void mbar_init(void* m, uint32_t cnt) {
    asm volatile("mbarrier.init.shared.b64 [%0], %1;"
                 :: "r"(sm32(m)), "r"(cnt) : "memory");
}
__device__ __forceinline__ void mbar_expect(void* m, uint32_t bytes) {
    asm volatile("mbarrier.arrive.expect_tx.shared.b64 _, [%0], %1;"
                 :: "r"(sm32(m)), "r"(bytes) : "memory");
}
__device__ __forceinline__ void bulk_g2s(void* dst, const void* src,
                                         uint32_t bytes, void* m) {
    asm volatile(
        "cp.async.bulk.shared::cta.global.mbarrier::complete_tx::bytes "
        "[%0], [%1], %2, [%3];"
        :: "r"(sm32(dst)), "l"(src), "r"(bytes), "r"(sm32(m)) : "memory");
}
__device__ __forceinline__ void mbar_wait(void* m, uint32_t parity) {
    uint32_t addr = sm32(m);
    asm volatile(
        "{\n\t"
        ".reg .pred P;\n\t"
        "WLP%=:\n\t"
        "mbarrier.try_wait.parity.acquire.cta.shared::cta.b64 P, [%0], %1, 0x989680;\n\t"
        "@P bra WDN%=;\n\t"
        "bra WLP%=;\n\t"
        "WDN%=:\n\t"
        "}"
        :: "r"(addr), "r"(parity) : "memory");
}

// ================= prep1: permute + mask + transpose weights ================
__global__ void prep_kernel(const float* __restrict__ W0, const float* __restrict__ b0,
                            const float* __restrict__ W1, const float* __restrict__ b1,
                            const float* __restrict__ W2) {
    const int N0 = U_ * D_;
    const int N1 = U_;
    const int N2 = U_;
    const int N3 = U_ * U_;
    const int N4 = U_ * 2 * D_;
    int i = blockIdx.x * blockDim.x + threadIdx.x;
    if (i < N0) {
        int j = i >> 6, d = i & 63, v;
        int pu = perm_of(j, v);
        g_W0p[i] = (d <= v) ? W0[pu * D_ + d] : 0.f;
    } else if (i < N0 + N1) {
        int j = i - N0, v; int pu = perm_of(j, v);
        g_b0p[j] = b0[pu];
    } else if (i < N0 + N1 + N2) {
        int j = i - N0 - N1, v; int pu = perm_of(j, v);
        g_b1p[j] = b1[pu];
    } else if (i < N0 + N1 + N2 + N3) {
        int k = i - (N0 + N1 + N2);
        int c = k >> 10, r = k & 1023;
        int vc, vr;
        int pc = perm_of(c, vc);
        int pr = perm_of(r, vr);
        g_W1pT[k] = (vr >= vc) ? W1[pr * U_ + pc] : 0.f;
    } else if (i < N0 + N1 + N2 + N3 + N4) {
        int k = i - (N0 + N1 + N2 + N3);
        int c = k >> 7, o = k & 127;
        int vc; int pc = perm_of(c, vc);
        g_W2pT[k] = (vc < (o & 63)) ? W2[o * U_ + pc] : 0.f;
    }
}

// ============ prep2: build A-fragment register images (fp16) ================
__global__ void prep2_kernel() {
    int idx = blockIdx.x * blockDim.x + threadIdx.x;
    if (idx >= 63 * 32 * 4 * 32) return;
    const int lane = idx & 31, frag = idx >> 5;
    const int kc = frag & 1, mt = (frag >> 1) & 1;
    const int w = (frag >> 2) & 31, v = frag >> 7;
    const int s0 = band_s0(v), cnt = band_cnt(v);
    const int r0 = 32 * w + 16 * mt + (lane >> 2);
    const int k0 = 2 * (lane & 3);
    unsigned rg[4];
#pragma unroll
    for (int j = 0; j < 4; j++) {
        const int r = r0 + 8 * (j & 1);
        const int k = k0 + 8 * (j >> 1);
        const int c0 = 16 * kc + k, c1 = c0 + 1;
        float f0 = (c0 < cnt) ? g_W1pT[(s0 + c0) * U_ + r] : 0.f;
        float f1 = (c1 < cnt) ? g_W1pT[(s0 + c1) * U_ + r] : 0.f;
        unsigned u0 = (unsigned)__half_as_ushort(__float2half(f0));
        unsigned u1 = (unsigned)__half_as_ushort(__float2half(f1));
        rg[j] = u0 | (u1 << 16);
    }
    g_W1f[frag * 32 + lane] = make_uint4(rg[0], rg[1], rg[2], rg[3]);
}

// ===================== shared-memory layout (floats) ========================
#define OFF_W0  0                         // 2*17*64 = 2176
#define OFF_W2  2176                      // 3*17*128 = 6528
#define OFF_Z   8704                      // 128*18 = 2304
#define OFF_X   11008                     // 64*17 = 1088
#define OFF_U   12096                     // 16*65 = 1040
#define OFF_H1  13136                     // 17*16 = 272
#define OFF_BF  13408                     // 4 frags * 64 u32 = 256
#define OFF_B0S 13664                     // 1024
#define OFF_B1S 14688                     // 1024
#define OFF_B2S 15712                     // 128
#define SMEM_FLOATS 15840                 // 63360 bytes

// ============================= main kernel ==================================
__global__ __launch_bounds__(NTH, 2)
void made_kernel(const float* __restrict__ u, const float* __restrict__ b2,
                 float* __restrict__ out) {
    extern __shared__ __align__(16) float smf[];
    __shared__ __align__(8) unsigned long long mbars[5];  // [0..1]=W0, [2..4]=W2 ring

    float* w0b  = smf + OFF_W0;
    float* w2b  = smf + OFF_W2;
    float* zsm  = smf + OFF_Z;
    float* x_sm = smf + OFF_X;
    float* u_sm = smf + OFF_U;
    float* h1b  = smf + OFF_H1;
    float* b0s  = smf + OFF_B0S;
    float* b1s  = smf + OFF_B1S;
    float* b2s  = smf + OFF_B2S;
    uint2* bfsm = (uint2*)(smf + OFF_BF);   // B-frag f at bfsm[f*32 + lane]
    __half* bfh = (__half*)(smf + OFF_BF);

    const int tid   = threadIdx.x;
    const int lane  = tid & 31;
    const int wid   = tid >> 5;             // 0..15
    const int sbase = blockIdx.x * SPB;

    for (int k = tid; k < 128 * PADZ; k += NTH) zsm[k] = 0.f;
    for (int k = tid; k < SPB * D_; k += NTH) {
        int s = k >> 6, d = k & 63;
        u_sm[s * PADU + d] = u[(sbase + s) * D_ + d];
    }
    for (int k = tid; k < U_; k += NTH) { b0s[k] = g_b0p[k]; b1s[k] = g_b1p[k]; }
    if (tid < 128) b2s[tid] = b2[tid];
    // zero B-frag image once (unwritten sub-slots must stay zero)
    if (tid < 128) ((float2*)(smf + OFF_BF))[tid] = make_float2(0.f, 0.f);
    if (tid == 0) {
#pragma unroll
        for (int m = 0; m < 5; m++) mbar_init(&mbars[m], 1);
    }

    // persistent mma accumulators: warp owns rows 64*wid .. 64*wid+63
    float acc[4][2][4];
#pragma unroll
    for (int a = 0; a < 4; a++)
#pragma unroll
        for (int b = 0; b < 2; b++)
#pragma unroll
            for (int c = 0; c < 4; c++) acc[a][b][c] = 0.f;

    float ldj = 0.f;
    __syncthreads();

    for (int i = 0; i < D_; i++) {
        const int v = i - 1;
        int s0 = 0, cnt = 0;
        if (i > 0) { s0 = band_s0(v); cnt = band_cnt(v); }

        // ---- DMA prefetch band v=i (W0 for step i+1, W2 for steps i+1/i+2) ----
        if (i < 63 && tid == 0) {
            const int s0p = band_s0(i), cntp = band_cnt(i);
            void* mb = &mbars[i & 1];
            mbar_expect(mb, (uint32_t)(cntp * 256));
            bulk_g2s(w0b + (i & 1) * (17 * 64), g_W0p + s0p * 64,
                     (uint32_t)(cntp * 256), mb);
            void* mb2 = &mbars[2 + (i % 3)];
            mbar_expect(mb2, (uint32_t)(cntp * 512));
            bulk_g2s(w2b + (i % 3) * (17 * 128), g_W2pT + s0p * 128,
                     (uint32_t)(cntp * 512), mb2);
        }
        if (i >= 1) {
            mbar_wait(&mbars[(i - 1) & 1], ((i - 1) >> 1) & 1);        // W0 band v
            mbar_wait(&mbars[2 + (i - 1) % 3], ((i - 1) / 3) & 1);     // W2 band v (E)
        }
        if (i >= 2) {
            mbar_wait(&mbars[2 + (i - 2) % 3], ((i - 2) / 3) & 1);     // W2 band v-1 (D)
        }

        // =============== P1: A (h0 band -> B-frag image) || D (z scatter) ===============
        if (i > 0) {
            if (wid < 9) {
                // ---- A: band col c = 2*wid + (lane>>4), sample s = lane&15 ----
                const int c = 2 * wid + (lane >> 4);
                const int s = lane & 15;
                if (c < cnt) {
                    const float* wr = w0b + (v & 1) * (17 * 64) + c * 64;
                    float a0 = 0.f, a1 = 0.f, a2 = 0.f, a3 = 0.f;
                    int d = 0;
#pragma unroll 4
                    for (; d + 4 <= i; d += 4) {
                        a0 = fmaf(wr[d],     x_sm[d * PADX + s],       a0);
                        a1 = fmaf(wr[d + 1], x_sm[(d + 1) * PADX + s], a1);
                        a2 = fmaf(wr[d + 2], x_sm[(d + 2) * PADX + s], a2);
                        a3 = fmaf(wr[d + 3], x_sm[(d + 3) * PADX + s], a3);
                    }
                    for (; d < i; d++)
                        a0 = fmaf(wr[d], x_sm[d * PADX + s], a0);
                    const float h = fmaxf(b0s[s0 + c] + (a0 + a1) + (a2 + a3), 0.f);
                    // write into fp16 B-frag register image
                    const int kc = c >> 4, jj = c & 15, jj8 = jj & 7;
                    const int nt = s >> 3, n8 = s & 7;
                    const int l  = (n8 << 2) | (jj8 >> 1);
                    const int bsel = jj >> 3, half = jj & 1;
                    const int word = (2 * nt + kc) * 64 + l * 2 + bsel;
                    bfh[word * 2 + half] = __float2half(h);
                }
            } else if (wid >= 12 && i >= 2) {
                // ---- D: scatter h1 band v-1 into live z rows (thread = z row) ----
                const int vD = i - 2;
                const int cntD = band_cnt(vD);
                const int o = tid - 384;          // 0..127
                if ((o & 63) >= i) {
                    unsigned long long* zp = (unsigned long long*)(zsm + o * PADZ);
                    unsigned long long z0 = zp[0], z1 = zp[1], z2 = zp[2], z3 = zp[3];
                    unsigned long long z4 = zp[4], z5 = zp[5], z6 = zp[6], z7 = zp[7];
                    const float* w2c = w2b + (vD % 3) * (17 * 128) + o;
                    float wv[17];
#pragma unroll
                    for (int c = 0; c < 16; c++) wv[c] = w2c[c * 128];
                    wv[16] = (cntD == 17) ? w2c[16 * 128] : 0.f;
#pragma unroll
                    for (int c = 0; c < 17; c++) {
                        const unsigned long long wp = pack2(wv[c], wv[c]);
                        const ulonglong2* hp = (const ulonglong2*)(h1b + c * 16);
                        ulonglong2 ha = hp[0], hb = hp[1], hc = hp[2], hd = hp[3];
                        fma_f32x2(z0, wp, ha.x); fma_f32x2(z1, wp, ha.y);
                        fma_f32x2(z2, wp, hb.x); fma_f32x2(z3, wp, hb.y);
                        fma_f32x2(z4, wp, hc.x); fma_f32x2(z5, wp, hc.y);
                        fma_f32x2(z6, wp, hd.x); fma_f32x2(z7, wp, hd.y);
                    }
                    zp[0] = z0; zp[1] = z1; zp[2] = z2; zp[3] = z3;
                    zp[4] = z4; zp[5] = z5; zp[6] = z6; zp[7] = z7;
                }
            }
        }
        __syncthreads();

        // =============== P2: B (tensor-core rank-cnt update) + C (extract) ===============
        if (i > 0 && wid >= (s0 >> 6)) {
            // B-frags: f = 2*nt + kc
            uint2 b00 = bfsm[0 * 32 + lane];     // nt0 kc0
            uint2 b10 = bfsm[2 * 32 + lane];     // nt1 kc0
#pragma unroll
            for (int m = 0; m < 4; m++) {
                if (64 * wid + 16 * m + 16 > s0) {   // tile intersects live rows
                    const uint4* fp = g_W1f +
                        ((size_t)((v * 32 + 2 * wid + (m >> 1)) * 4 + (m & 1) * 2)) * 32 + lane;
                    uint4 A0 = fp[0];                 // kc0
                    mma_f16(acc[m][0], A0, b00);
                    mma_f16(acc[m][1], A0, b10);
                    if (cnt == 17) {
                        uint4 A1 = fp[32];            // kc1
                        uint2 c00 = bfsm[1 * 32 + lane];
                        uint2 c10 = bfsm[3 * 32 + lane];
                        mma_f16(acc[m][0], A1, c00);
                        mma_f16(acc[m][1], A1, c10);
                    }
                }
            }
            // ---- C: extract newly-complete h1 band (bias + relu -> smem) ----
            const int rbase = 64 * wid;
            if (rbase < s0 + cnt && rbase + 63 >= s0) {
#pragma unroll
                for (int m = 0; m < 4; m++) {
                    const int ra = rbase + 16 * m + (lane >> 2);
#pragma unroll
                    for (int hh = 0; hh < 2; hh++) {
                        const int r = ra + 8 * hh;
                        if (r >= s0 && r < s0 + cnt) {
                            const int c = r - s0;
                            const float bb = b1s[r];
#pragma unroll
                            for (int nt = 0; nt < 2; nt++) {
                                const int n0 = 8 * nt + 2 * (lane & 3);
                                float2 val;
                                val.x = fmaxf(bb + acc[m][nt][2 * hh],     0.f);
                                val.y = fmaxf(bb + acc[m][nt][2 * hh + 1], 0.f);
                                *(float2*)(h1b + c * 16 + n0) = val;
                            }
                        }
                    }
                }
            }
        }
        __syncthreads();

        // =============== P3: E — emit x[i], accumulate log-det (warp 0) ===============
        if (wid == 0 && lane < SPB) {
            float mu = zsm[i * PADZ + lane];
            float sg = zsm[(64 + i) * PADZ + lane];
            if (i > 0) {
                const float* w2e = w2b + (v % 3) * (17 * 128);
#pragma unroll
                for (int c = 0; c < 16; c++) {
                    const float hv = h1b[c * 16 + lane];
                    mu = fmaf(w2e[c * 128 + i], hv, mu);
                    sg = fmaf(w2e[c * 128 + 64 + i], hv, sg);
                }
                if (cnt == 17) {
                    const float hv = h1b[16 * 16 + lane];
                    mu = fmaf(w2e[16 * 128 + i], hv, mu);
                    sg = fmaf(w2e[16 * 128 + 64 + i], hv, sg);
                }
            }
            mu += b2s[i];
            sg += b2s[64 + i];
            const float xv = fmaf(u_sm[lane * PADU + i], __expf(sg), mu);
            x_sm[i * PADX + lane] = xv;
            ldj += sg;
        }
        __syncthreads();
    }

    // ---- outputs: x [B,64] then ldj [B,1] ----
    for (int k = tid; k < SPB * D_; k += NTH) {
        const int s = k >> 6, d = k & 63;
        out[(sbase + s) * D_ + d] = x_sm[d * PADX + s];
    }
    if (tid < SPB) out[B_ * D_ + sbase + tid] = ldj;
}

// ============================== launch ======================================
extern "C" void kernel_launch(void* const* d_in, const int* in_sizes, int n_in,
                              void* d_out, int out_size) {
    const float* u  = (const float*)d_in[0];
    const float* W0 = (const float*)d_in[1];
    const float* b0 = (const float*)d_in[2];
    const float* W1 = (const float*)d_in[3];
    const float* b1 = (const float*)d_in[4];
    const float* W2 = (const float*)d_in[5];
    const float* b2 = (const float*)d_in[6];
    float* out = (float*)d_out;

    cudaFuncSetAttribute(made_kernel,
                         cudaFuncAttributeMaxDynamicSharedMemorySize,
                         SMEM_FLOATS * 4);

    const int total = U_ * D_ + U_ + U_ + U_ * U_ + U_ * 2 * D_;
    prep_kernel<<<(total + 255) / 256, 256>>>(W0, b0, W1, b1, W2);
    prep2_kernel<<<(63 * 32 * 4 * 32 + 255) / 256, 256>>>();
    made_kernel<<<B_ / SPB, NTH, SMEM_FLOATS * 4>>>(u, b2, out);
}

// round 17
// speedup vs baseline: 1.1374x; 1.1374x over previous
#include <cuda_runtime.h>
#include <cuda_fp16.h>
#include <math.h>
#include <stdint.h>

#define U_   1024
#define D_   64
#define B_   4096
#define SPB  32
#define PADX 33
#define PADU 65
#define PADZ 36

// ---- device-global weight scratch (no allocs allowed) ----
__device__ float g_W0p[U_ * D_];        // masked W0, rows sorted by dh (bands contiguous)
__device__ float g_b0p[U_];
__device__ float g_b1p[U_];
__device__ float g_W1pT[U_ * U_];       // [c][r] masked W1^T, both perm'd (intermediate)
__device__ float g_W2pT[U_ * 2 * D_];   // [c][o] masked W2^T (band rows contiguous)
// A-fragment register images (fp16): frag id = ((v*32+w)*2+mt)*2+kc, 32 lanes of uint4
__device__ uint4 g_W1f[63 * 32 * 2 * 2 * 32];

// units sorted by dh = u % 63
__device__ __forceinline__ int perm_of(int j, int& v) {
    int t;
    if (j < 272) { v = j / 17; t = j - v * 17; }
    else         { v = (j - 16) >> 4; t = (j - 16) & 15; }
    return v + 63 * t;
}
__device__ __forceinline__ int band_s0(int v)  { return (v <= 16) ? 17 * v : 16 * v + 16; }
__device__ __forceinline__ int band_cnt(int v) { return (v < 16) ? 17 : 16; }

// ---- packed fp32x2 helpers (Phase D) ----
__device__ __forceinline__ unsigned long long pack2(float lo, float hi) {
    unsigned long long r;
    asm("mov.b64 %0, {%1, %2};" : "=l"(r) : "f"(lo), "f"(hi));
    return r;
}
__device__ __forceinline__ void fma_f32x2(unsigned long long& d,
                                          unsigned long long a,
                                          unsigned long long b) {
    asm("fma.rn.f32x2 %0, %1, %2, %0;" : "+l"(d) : "l"(a), "l"(b));
}

// ---- mma fp16 helper ----
__device__ __forceinline__ void mma_f16(float* d, const uint4& a, const uint2& b) {
    asm volatile(
        "mma.sync.aligned.m16n8k16.row.col.f32.f16.f16.f32 "
        "{%0,%1,%2,%3},{%4,%5,%6,%7},{%8,%9},{%0,%1,%2,%3};"
        : "+f"(d[0]), "+f"(d[1]), "+f"(d[2]), "+f"(d[3])
        : "r"(a.x), "r"(a.y), "r"(a.z), "r"(a.w), "r"(b.x), "r"(b.y));
}

// ---- mbarrier / bulk-copy helpers ----
__device__ __forceinline__ uint32_t sm32(const void* p) {
    uint32_t a;
    asm("{ .reg .u64 t; cvta.to.shared.u64 t, %1; cvt.u32.u64 %0, t; }"
        : "=r"(a) : "l"(p));
    return a;
}
__device__ __forceinline__ void mbar_init(void* m, uint32_t cnt) {
    asm volatile("mbarrier.init.shared.b64 [%0], %1;"
                 :: "r"(sm32(m)), "r"(cnt) : "memory");
}
__device__ __forceinline__ void mbar_expect(void* m, uint32_t bytes) {
    asm volatile("mbarrier.arrive.expect_tx.shared.b64 _, [%0], %1;"
                 :: "r"(sm32(m)), "r"(bytes) : "memory");
}
__device__ __forceinline__ void bulk_g2s(void* dst, const void* src,
                                         uint32_t bytes, void* m) {
    asm volatile(
        "cp.async.bulk.shared::cta.global.mbarrier::complete_tx::bytes "
        "[%0], [%1], %2, [%3];"
        :: "r"(sm32(dst)), "l"(src), "r"(bytes), "r"(sm32(m)) : "memory");
}
__device__ __forceinline__ void mbar_wait(void* m, uint32_t parity) {
    uint32_t addr = sm32(m);
    asm volatile(
        "{\n\t"
        ".reg .pred P;\n\t"
        "WLP%=:\n\t"
        "mbarrier.try_wait.parity.acquire.cta.shared::cta.b64 P, [%0], %1, 0x989680;\n\t"
        "@P bra WDN%=;\n\t"
        "bra WLP%=;\n\t"
        "WDN%=:\n\t"
        "}"
        :: "r"(addr), "r"(parity) : "memory");
}

// ================= prep1: permute + mask + transpose weights ================
__global__ void prep_kernel(const float* __restrict__ W0, const float* __restrict__ b0,
                            const float* __restrict__ W1, const float* __restrict__ b1,
                            const float* __restrict__ W2) {
    const int N0 = U_ * D_;
    const int N1 = U_;
    const int N2 = U_;
    const int N3 = U_ * U_;
    const int N4 = U_ * 2 * D_;
    int i = blockIdx.x * blockDim.x + threadIdx.x;
    if (i < N0) {
        int j = i >> 6, d = i & 63, v;
        int pu = perm_of(j, v);
        g_W0p[i] = (d <= v) ? W0[pu * D_ + d] : 0.f;
    } else if (i < N0 + N1) {
        int j = i - N0, v; int pu = perm_of(j, v);
        g_b0p[j] = b0[pu];
    } else if (i < N0 + N1 + N2) {
        int j = i - N0 - N1, v; int pu = perm_of(j, v);
        g_b1p[j] = b1[pu];
    } else if (i < N0 + N1 + N2 + N3) {
        int k = i - (N0 + N1 + N2);
        int c = k >> 10, r = k & 1023;
        int vc, vr;
        int pc = perm_of(c, vc);
        int pr = perm_of(r, vr);
        g_W1pT[k] = (vr >= vc) ? W1[pr * U_ + pc] : 0.f;
    } else if (i < N0 + N1 + N2 + N3 + N4) {
        int k = i - (N0 + N1 + N2 + N3);
        int c = k >> 7, o = k & 127;
        int vc; int pc = perm_of(c, vc);
        g_W2pT[k] = (vc < (o & 63)) ? W2[o * U_ + pc] : 0.f;
    }
}

// ============ prep2: build A-fragment register images (fp16) ================
__global__ void prep2_kernel() {
    int idx = blockIdx.x * blockDim.x + threadIdx.x;
    if (idx >= 63 * 32 * 4 * 32) return;
    const int lane = idx & 31, frag = idx >> 5;
    const int kc = frag & 1, mt = (frag >> 1) & 1;
    const int w = (frag >> 2) & 31, v = frag >> 7;
    const int s0 = band_s0(v), cnt = band_cnt(v);
    const int r0 = 32 * w + 16 * mt + (lane >> 2);
    const int k0 = 2 * (lane & 3);
    unsigned rg[4];
#pragma unroll
    for (int j = 0; j < 4; j++) {
        const int r = r0 + 8 * (j & 1);
        const int k = k0 + 8 * (j >> 1);
        const int c0 = 16 * kc + k, c1 = c0 + 1;
        float f0 = (c0 < cnt) ? g_W1pT[(s0 + c0) * U_ + r] : 0.f;
        float f1 = (c1 < cnt) ? g_W1pT[(s0 + c1) * U_ + r] : 0.f;
        unsigned u0 = (unsigned)__half_as_ushort(__float2half(f0));
        unsigned u1 = (unsigned)__half_as_ushort(__float2half(f1));
        rg[j] = u0 | (u1 << 16);
    }
    g_W1f[frag * 32 + lane] = make_uint4(rg[0], rg[1], rg[2], rg[3]);
}

// ===================== shared-memory layout (floats) ========================
#define OFF_W0 0                          // 2*17*64 = 2176
#define OFF_W2 2176                       // 3*17*128 = 6528
#define OFF_Z  8704                       // 128*36 = 4608
#define OFF_X  13312                      // 64*33 = 2112
#define OFF_U  15424                      // 32*65 = 2080
#define OFF_H1 17504                      // 17*32 = 544
#define OFF_BF 18048                      // 8 frags * 64 u32 = 512 (1024 reserved)
#define OFF_B0S 19072                     // 1024
#define OFF_B1S 20096                     // 1024
#define OFF_B2S 21120                     // 128
#define SMEM_FLOATS 21248                 // 84992 bytes

// ============================= main kernel ==================================
__global__ __launch_bounds__(1024, 1)
void made_kernel(const float* __restrict__ u, const float* __restrict__ b2,
                 float* __restrict__ out) {
    extern __shared__ __align__(16) float smf[];
    __shared__ __align__(8) unsigned long long mbars[5];  // [0..1]=W0, [2..4]=W2 ring

    float* w0b  = smf + OFF_W0;
    float* w2b  = smf + OFF_W2;
    float* zsm  = smf + OFF_Z;
    float* x_sm = smf + OFF_X;
    float* u_sm = smf + OFF_U;
    float* h1b  = smf + OFF_H1;
    float* b0s  = smf + OFF_B0S;
    float* b1s  = smf + OFF_B1S;
    float* b2s  = smf + OFF_B2S;
    uint2* bfsm = (uint2*)(smf + OFF_BF);   // B-frag f at bfsm[f*32 + lane]
    __half* bfh = (__half*)(smf + OFF_BF);

    const int tid   = threadIdx.x;
    const int lane  = tid & 31;
    const int wid   = tid >> 5;
    const int sbase = blockIdx.x * SPB;

    for (int k = tid; k < 128 * PADZ; k += 1024) zsm[k] = 0.f;
    for (int k = tid; k < SPB * D_; k += 1024) {
        int s = k >> 6, d = k & 63;
        u_sm[s * PADU + d] = u[(sbase + s) * D_ + d];
    }
    b0s[tid] = g_b0p[tid];
    b1s[tid] = g_b1p[tid];
    if (tid < 128) b2s[tid] = b2[tid];
    // zero B-frag image once (unwritten kc1 sub-slots must stay zero)
    if (tid < 512) ((float2*)(smf + OFF_BF))[tid] = make_float2(0.f, 0.f);
    if (tid == 0) {
#pragma unroll
        for (int m = 0; m < 5; m++) mbar_init(&mbars[m], 1);
    }

    // persistent mma accumulators: this warp owns rows 32*wid .. 32*wid+31
    float acc[2][4][4];
#pragma unroll
    for (int a = 0; a < 2; a++)
#pragma unroll
        for (int b = 0; b < 4; b++)
#pragma unroll
            for (int c = 0; c < 4; c++) acc[a][b][c] = 0.f;

    float ldj = 0.f;
    __syncthreads();

    for (int i = 0; i < D_; i++) {
        const int v = i - 1;
        int s0 = 0, cnt = 0;
        if (i > 0) { s0 = band_s0(v); cnt = band_cnt(v); }

        // ---- DMA prefetch band v=i (W0 for step i+1, W2 for steps i+1/i+2) ----
        if (i < 63 && tid == 0) {
            const int s0p = band_s0(i), cntp = band_cnt(i);
            void* mb = &mbars[i & 1];
            mbar_expect(mb, (uint32_t)(cntp * 256));
            bulk_g2s(w0b + (i & 1) * (17 * 64), g_W0p + s0p * 64,
                     (uint32_t)(cntp * 256), mb);
            void* mb2 = &mbars[2 + (i % 3)];
            mbar_expect(mb2, (uint32_t)(cntp * 512));
            bulk_g2s(w2b + (i % 3) * (17 * 128), g_W2pT + s0p * 128,
                     (uint32_t)(cntp * 512), mb2);
        }

        // ---- early A-frag prefetch (kc0 planes) for P2-active warps ----
        const bool p2act = (i > 0) && (wid >= (s0 >> 5));
        const uint4* fb = nullptr;
        uint4 A0, A1;
        if (p2act) {
            fb = g_W1f + (size_t)((v * 32 + wid) * 4) * 32 + lane;
            A0 = fb[0 * 32];          // mt=0, kc=0
            A1 = fb[2 * 32];          // mt=1, kc=0
        }

        // =============== P1: A (h0 band -> B-frag image) || D (z scatter) ===============
        if (i > 0) {
            if (wid < cnt) {
                // A warps consume W0 band v (DMA'd at step i-1): scoped wait
                mbar_wait(&mbars[(i - 1) & 1], ((i - 1) >> 1) & 1);
                // ---- A: finalize h0 row (s0+wid), sample=lane ----
                const float* wr = w0b + (v & 1) * (17 * 64) + wid * 64;
                float a0 = 0.f, a1 = 0.f, a2 = 0.f, a3 = 0.f;
                int d = 0;
#pragma unroll 4
                for (; d + 4 <= i; d += 4) {
                    a0 = fmaf(wr[d],     x_sm[d * PADX + lane],       a0);
                    a1 = fmaf(wr[d + 1], x_sm[(d + 1) * PADX + lane], a1);
                    a2 = fmaf(wr[d + 2], x_sm[(d + 2) * PADX + lane], a2);
                    a3 = fmaf(wr[d + 3], x_sm[(d + 3) * PADX + lane], a3);
                }
                for (; d < i; d++)
                    a0 = fmaf(wr[d], x_sm[d * PADX + lane], a0);
                const float h = fmaxf(b0s[s0 + wid] + (a0 + a1) + (a2 + a3), 0.f);
                // write into fp16 B-frag register image
                const int c  = wid;
                const int kc = c >> 4, jj = c & 15, jj8 = jj & 7;
                const int nt = lane >> 3, n8 = lane & 7;
                const int l  = (n8 << 2) | (jj8 >> 1);
                const int bsel = jj >> 3, half = jj & 1;
                const int word = (2 * nt + kc) * 64 + l * 2 + bsel;
                bfh[word * 2 + half] = __float2half(h);
            } else if (wid >= 24 && i >= 2) {
                // ---- D: scatter h1 band v-1 into live z rows ----
                const int vD = i - 2;
                const int cntD = band_cnt(vD);
                const int t = tid - 768;
                const int o = t >> 1;
                const int half = t & 1;
                if ((o & 63) >= i) {
                    // D consumes W2 ring slot for band vD: scoped wait
                    mbar_wait(&mbars[2 + vD % 3], (vD / 3) & 1);
                    unsigned long long* zp =
                        (unsigned long long*)(zsm + o * PADZ + half * 16);
                    unsigned long long z0 = zp[0], z1 = zp[1], z2 = zp[2], z3 = zp[3];
                    unsigned long long z4 = zp[4], z5 = zp[5], z6 = zp[6], z7 = zp[7];
                    const float* w2c = w2b + (vD % 3) * (17 * 128) + o;
                    float wv[17];
#pragma unroll
                    for (int c = 0; c < 16; c++) wv[c] = w2c[c * 128];
                    wv[16] = (cntD == 17) ? w2c[16 * 128] : 0.f;
#pragma unroll
                    for (int c = 0; c < 17; c++) {
                        const unsigned long long wp = pack2(wv[c], wv[c]);
                        const ulonglong2* hp =
                            (const ulonglong2*)(h1b + c * 32 + half * 16);
                        ulonglong2 ha = hp[0], hb = hp[1], hc = hp[2], hd = hp[3];
                        fma_f32x2(z0, wp, ha.x); fma_f32x2(z1, wp, ha.y);
                        fma_f32x2(z2, wp, hb.x); fma_f32x2(z3, wp, hb.y);
                        fma_f32x2(z4, wp, hc.x); fma_f32x2(z5, wp, hc.y);
                        fma_f32x2(z6, wp, hd.x); fma_f32x2(z7, wp, hd.y);
                    }
                    zp[0] = z0; zp[1] = z1; zp[2] = z2; zp[3] = z3;
                    zp[4] = z4; zp[5] = z5; zp[6] = z6; zp[7] = z7;
                }
            }
        }
        __syncthreads();

        // =============== P2: B (tensor-core rank-cnt update) + C (extract) ===============
        if (p2act) {
            // ---- kc = 0 (band cols 0..15) ----
#pragma unroll
            for (int nt = 0; nt < 4; nt++) {
                uint2 b = bfsm[(2 * nt) * 32 + lane];
                mma_f16(acc[0][nt], A0, b);
                mma_f16(acc[1][nt], A1, b);
            }
            // ---- kc = 1 (col 16, only when band has 17 units) ----
            if (cnt == 17) {
                uint4 B0 = fb[1 * 32];
                uint4 B1 = fb[3 * 32];
#pragma unroll
                for (int nt = 0; nt < 4; nt++) {
                    uint2 b = bfsm[(2 * nt + 1) * 32 + lane];
                    mma_f16(acc[0][nt], B0, b);
                    mma_f16(acc[1][nt], B1, b);
                }
            }
            // ---- C: extract newly-complete h1 band (bias + relu -> smem) ----
            const int rbase = 32 * wid;
            if (rbase < s0 + cnt && rbase + 31 >= s0) {
#pragma unroll
                for (int mt = 0; mt < 2; mt++) {
                    const int ra = rbase + 16 * mt + (lane >> 2);
#pragma unroll
                    for (int hh = 0; hh < 2; hh++) {
                        const int r = ra + 8 * hh;
                        if (r >= s0 && r < s0 + cnt) {
                            const int c = r - s0;
                            const float bb = b1s[r];
#pragma unroll
                            for (int nt = 0; nt < 4; nt++) {
                                const int n0 = 8 * nt + 2 * (lane & 3);
                                float2 val;
                                val.x = fmaxf(bb + acc[mt][nt][2 * hh],     0.f);
                                val.y = fmaxf(bb + acc[mt][nt][2 * hh + 1], 0.f);
                                *(float2*)(h1b + c * 32 + n0) = val;
                            }
                        }
                    }
                }
            }
        }
        __syncthreads();

        // =============== P3: E — emit x[i], accumulate log-det (warp 0) ===============
        if (wid == 0) {
            float mu = zsm[i * PADZ + lane];
            float sg = zsm[(64 + i) * PADZ + lane];
            if (i > 0) {
                // E consumes W2 ring slot for band v: scoped wait
                mbar_wait(&mbars[2 + v % 3], (v / 3) & 1);
                const float* w2e = w2b + (v % 3) * (17 * 128);
#pragma unroll
                for (int c = 0; c < 16; c++) {
                    const float hv = h1b[c * 32 + lane];
                    mu = fmaf(w2e[c * 128 + i], hv, mu);
                    sg = fmaf(w2e[c * 128 + 64 + i], hv, sg);
                }
                if (cnt == 17) {
                    const float hv = h1b[16 * 32 + lane];
                    mu = fmaf(w2e[16 * 128 + i], hv, mu);
                    sg = fmaf(w2e[16 * 128 + 64 + i], hv, sg);
                }
            }
            mu += b2s[i];
            sg += b2s[64 + i];
            const float xv = fmaf(u_sm[lane * PADU + i], __expf(sg), mu);
            x_sm[i * PADX + lane] = xv;
            ldj += sg;
        }
        __syncthreads();
    }

    // ---- outputs: x [B,64] then ldj [B,1] ----
    for (int k = tid; k < SPB * D_; k += 1024) {
        const int s = k >> 6, d = k & 63;
        out[(sbase + s) * D_ + d] = x_sm[d * PADX + s];
    }
    if (tid < 32) out[B_ * D_ + sbase + tid] = ldj;
}

// ============================== launch ======================================
extern "C" void kernel_launch(void* const* d_in, const int* in_sizes, int n_in,
                              void* d_out, int out_size) {
    const float* u  = (const float*)d_in[0];
    const float* W0 = (const float*)d_in[1];
    const float* b0 = (const float*)d_in[2];
    const float* W1 = (const float*)d_in[3];
    const float* b1 = (const float*)d_in[4];
    const float* W2 = (const float*)d_in[5];
    const float* b2 = (const float*)d_in[6];
    float* out = (float*)d_out;

    cudaFuncSetAttribute(made_kernel,
                         cudaFuncAttributeMaxDynamicSharedMemorySize,
                         SMEM_FLOATS * 4);

    const int total = U_ * D_ + U_ + U_ + U_ * U_ + U_ * 2 * D_;
    prep_kernel<<<(total + 255) / 256, 256>>>(W0, b0, W1, b1, W2);
    prep2_kernel<<<(63 * 32 * 4 * 32 + 255) / 256, 256>>>();
    made_kernel<<<B_ / SPB, 1024, SMEM_FLOATS * 4>>>(u, b2, out);
}